// round 3
// baseline (speedup 1.0000x reference)
#include <cuda_runtime.h>

#define B_  4
#define S_  2048
#define D_  512
#define H_  8
#define DH_ 64
#define BH_ (B_ * H_)

typedef unsigned long long ull;

__device__ float g_q[B_ * H_ * S_ * DH_];
__device__ float g_k[B_ * H_ * S_ * DH_];
__device__ float g_v[B_ * H_ * S_ * DH_];

__device__ __forceinline__ ull ffma2(ull a, ull b, ull c) {
    ull d;
    asm("fma.rn.f32x2 %0, %1, %2, %3;" : "=l"(d) : "l"(a), "l"(b), "l"(c));
    return d;
}
__device__ __forceinline__ ull fmul2(ull a, ull b) {
    ull d;
    asm("mul.rn.f32x2 %0, %1, %2;" : "=l"(d) : "l"(a), "l"(b));
    return d;
}
__device__ __forceinline__ ull pack2(float lo, float hi) {
    ull d;
    asm("mov.b64 %0, {%1, %2};" : "=l"(d) : "f"(lo), "f"(hi));
    return d;
}
__device__ __forceinline__ float2 unpack2(ull v) {
    float lo, hi;
    asm("mov.b64 {%0, %1}, %2;" : "=f"(lo), "=f"(hi) : "l"(v));
    return make_float2(lo, hi);
}

// ---------------------------------------------------------------------------
// Kernel A: fused QKV projection, packed-FFMA2.
//   Tile 128(M) x 64(N), K=512, BK=16, 256 threads.
//   Micro-tile: 8 M (4 f32x2 pairs) x 4 N per thread.
//   Xs: k-major transposed [k][m] (natural M pairs).
//   Wd: duplicated [k][2n] so the scalar side loads as ready-made f32x2.
// ---------------------------------------------------------------------------
__global__ __launch_bounds__(256) void qkv_kernel(
    const float* __restrict__ x,
    const float* __restrict__ Wq,
    const float* __restrict__ Wk,
    const float* __restrict__ Wv)
{
    __shared__ float Xs[16 * 128];
    __shared__ float Wd[16 * 128];

    const int t  = threadIdx.x;
    const int tx = t & 15;               // n group: cols tx*4..+3
    const int ty = t >> 4;               // m group: rows ty*8..+7
    const int m0 = blockIdx.x * 128;
    const int wh = blockIdx.y;           // (weight)*8 + head
    const int w  = wh >> 3;
    const int h  = wh & 7;

    const float* W   = (w == 0 ? Wq : (w == 1 ? Wk : Wv)) + h * D_ * DH_;
    float*       out = (w == 0 ? g_q : (w == 1 ? g_k : g_v));

    const int xr = t >> 1;               // 0..127
    const int xc = (t & 1) * 8;          // k offset base
    const int wr = t >> 4;               // 0..15
    const int wc = (t & 15) * 4;         // 0..60

    ull acc[4][4] = {};

    for (int k0 = 0; k0 < D_; k0 += 16) {
        #pragma unroll
        for (int it = 0; it < 2; it++) {
            int c = xc + it * 4;
            float4 xv = *reinterpret_cast<const float4*>(&x[(m0 + xr) * D_ + k0 + c]);
            Xs[(c + 0) * 128 + xr] = xv.x;
            Xs[(c + 1) * 128 + xr] = xv.y;
            Xs[(c + 2) * 128 + xr] = xv.z;
            Xs[(c + 3) * 128 + xr] = xv.w;
        }
        {
            float4 wv = *reinterpret_cast<const float4*>(&W[(k0 + wr) * DH_ + wc]);
            *reinterpret_cast<ull*>(&Wd[wr * 128 + 2 * (wc + 0)]) = pack2(wv.x, wv.x);
            *reinterpret_cast<ull*>(&Wd[wr * 128 + 2 * (wc + 1)]) = pack2(wv.y, wv.y);
            *reinterpret_cast<ull*>(&Wd[wr * 128 + 2 * (wc + 2)]) = pack2(wv.z, wv.z);
            *reinterpret_cast<ull*>(&Wd[wr * 128 + 2 * (wc + 3)]) = pack2(wv.w, wv.w);
        }
        __syncthreads();

        #pragma unroll
        for (int kk = 0; kk < 16; kk++) {
            ulonglong2 A0 = *reinterpret_cast<const ulonglong2*>(&Xs[kk * 128 + ty * 8]);
            ulonglong2 A1 = *reinterpret_cast<const ulonglong2*>(&Xs[kk * 128 + ty * 8 + 4]);
            ulonglong2 B0 = *reinterpret_cast<const ulonglong2*>(&Wd[kk * 128 + tx * 8]);
            ulonglong2 B1 = *reinterpret_cast<const ulonglong2*>(&Wd[kk * 128 + tx * 8 + 4]);
            ull a[4] = {A0.x, A0.y, A1.x, A1.y};
            ull b[4] = {B0.x, B0.y, B1.x, B1.y};
            #pragma unroll
            for (int p = 0; p < 4; p++)
                #pragma unroll
                for (int j = 0; j < 4; j++)
                    acc[p][j] = ffma2(a[p], b[j], acc[p][j]);
        }
        __syncthreads();
    }

    #pragma unroll
    for (int p = 0; p < 4; p++) {
        float2 f0 = unpack2(acc[p][0]);
        float2 f1 = unpack2(acc[p][1]);
        float2 f2 = unpack2(acc[p][2]);
        float2 f3 = unpack2(acc[p][3]);
        int m_lo = m0 + ty * 8 + 2 * p;
        #pragma unroll
        for (int hh = 0; hh < 2; hh++) {
            int m = m_lo + hh;
            int b = m >> 11;
            int s = m & (S_ - 1);
            float4 o4 = hh == 0 ? make_float4(f0.x, f1.x, f2.x, f3.x)
                                : make_float4(f0.y, f1.y, f2.y, f3.y);
            *reinterpret_cast<float4*>(
                &out[(((b * H_ + h) * S_) + s) * DH_ + tx * 4]) = o4;
        }
    }
}

// ---------------------------------------------------------------------------
// Kernel B: flash attention, packed-FFMA2.
//   Q-tile 128, K-tile 64, 256 threads. Micro: 8 qi (4 pairs) x 4 kj / 4 d.
//   Qt : [d][qi]   transposed, scaled by DH^-0.5 (natural qi pairs)
//   Kd : [d][2kj]  duplicated
//   Vd : [kj][2d]  duplicated
//   Pt : [kj][qi]  transposed, stride 132 (natural qi pairs)
// ---------------------------------------------------------------------------
#define PPAD 132
#define ATTN_SMEM ((3 * 64 * 128 + 64 * PPAD) * 4)

__global__ __launch_bounds__(256, 1) void attn_kernel(float* __restrict__ out)
{
    extern __shared__ float sm[];
    float* Qt = sm;                    // 64*128
    float* Kd = sm + 64 * 128;         // 64*128
    float* Vd = sm + 2 * 64 * 128;     // 64*128
    float* Pt = sm + 3 * 64 * 128;     // 64*PPAD

    const int t  = threadIdx.x;
    const int tx = t & 15;             // kj group (S) / d group (O)
    const int ty = t >> 4;             // qi group
    const int q0 = blockIdx.x * 128;
    const int bh = blockIdx.y;

    const float* qp = g_q + bh * S_ * DH_;
    const float* kp = g_k + bh * S_ * DH_;
    const float* vp = g_v + bh * S_ * DH_;

    // Load Q tile, scaled, transposed: Qt[d][qi]
    {
        const int qi = t >> 1;
        #pragma unroll
        for (int it = 0; it < 8; it++) {
            int d0 = ((t & 1) * 8 + it) * 4;
            float4 qv = *reinterpret_cast<const float4*>(&qp[(q0 + qi) * DH_ + d0]);
            Qt[(d0 + 0) * 128 + qi] = qv.x * 0.125f;
            Qt[(d0 + 1) * 128 + qi] = qv.y * 0.125f;
            Qt[(d0 + 2) * 128 + qi] = qv.z * 0.125f;
            Qt[(d0 + 3) * 128 + qi] = qv.w * 0.125f;
        }
    }

    ull o[4][4] = {};
    float m_run[8], l_run[8];
    #pragma unroll
    for (int i = 0; i < 8; i++) { m_run[i] = -1e30f; l_run[i] = 0.0f; }

    const int kv_r = t >> 2;           // 0..63 (kj row)
    const int kv_c = (t & 3) * 16;     // d chunk base

    for (int kt = 0; kt < S_ / 64; kt++) {
        __syncthreads();               // prev iter readers done with Kd/Vd/Pt
        const int s0 = kt * 64;
        #pragma unroll
        for (int it = 0; it < 4; it++) {
            int d0 = kv_c + it * 4;
            float4 kv = *reinterpret_cast<const float4*>(&kp[(s0 + kv_r) * DH_ + d0]);
            float4 vv = *reinterpret_cast<const float4*>(&vp[(s0 + kv_r) * DH_ + d0]);
            *reinterpret_cast<ull*>(&Kd[(d0 + 0) * 128 + 2 * kv_r]) = pack2(kv.x, kv.x);
            *reinterpret_cast<ull*>(&Kd[(d0 + 1) * 128 + 2 * kv_r]) = pack2(kv.y, kv.y);
            *reinterpret_cast<ull*>(&Kd[(d0 + 2) * 128 + 2 * kv_r]) = pack2(kv.z, kv.z);
            *reinterpret_cast<ull*>(&Kd[(d0 + 3) * 128 + 2 * kv_r]) = pack2(kv.w, kv.w);
            *reinterpret_cast<ull*>(&Vd[kv_r * 128 + 2 * (d0 + 0)]) = pack2(vv.x, vv.x);
            *reinterpret_cast<ull*>(&Vd[kv_r * 128 + 2 * (d0 + 1)]) = pack2(vv.y, vv.y);
            *reinterpret_cast<ull*>(&Vd[kv_r * 128 + 2 * (d0 + 2)]) = pack2(vv.z, vv.z);
            *reinterpret_cast<ull*>(&Vd[kv_r * 128 + 2 * (d0 + 3)]) = pack2(vv.w, vv.w);
        }
        __syncthreads();

        // S = (Q*scale) @ K^T   (pairs along qi)
        ull sv[4][4] = {};
        #pragma unroll 8
        for (int d = 0; d < 64; d++) {
            ulonglong2 A0 = *reinterpret_cast<const ulonglong2*>(&Qt[d * 128 + ty * 8]);
            ulonglong2 A1 = *reinterpret_cast<const ulonglong2*>(&Qt[d * 128 + ty * 8 + 4]);
            ulonglong2 B0 = *reinterpret_cast<const ulonglong2*>(&Kd[d * 128 + tx * 8]);
            ulonglong2 B1 = *reinterpret_cast<const ulonglong2*>(&Kd[d * 128 + tx * 8 + 4]);
            ull a[4] = {A0.x, A0.y, A1.x, A1.y};
            ull b[4] = {B0.x, B0.y, B1.x, B1.y};
            #pragma unroll
            for (int p = 0; p < 4; p++)
                #pragma unroll
                for (int j = 0; j < 4; j++)
                    sv[p][j] = ffma2(a[p], b[j], sv[p][j]);
        }

        // Unpack to scalars for softmax
        float s[8][4];
        #pragma unroll
        for (int p = 0; p < 4; p++)
            #pragma unroll
            for (int j = 0; j < 4; j++) {
                float2 f = unpack2(sv[p][j]);
                s[2 * p + 0][j] = f.x;
                s[2 * p + 1][j] = f.y;
            }

        float alpha[8];
        #pragma unroll
        for (int i = 0; i < 8; i++) {
            float rm = fmaxf(fmaxf(s[i][0], s[i][1]), fmaxf(s[i][2], s[i][3]));
            #pragma unroll
            for (int off = 1; off < 16; off <<= 1)
                rm = fmaxf(rm, __shfl_xor_sync(0xffffffffu, rm, off));
            float mn = fmaxf(m_run[i], rm);
            alpha[i] = __expf(m_run[i] - mn);
            m_run[i] = mn;
            float rs = 0.0f;
            #pragma unroll
            for (int j = 0; j < 4; j++) {
                float p = __expf(s[i][j] - mn);
                s[i][j] = p;
                rs += p;
            }
            #pragma unroll
            for (int off = 1; off < 16; off <<= 1)
                rs += __shfl_xor_sync(0xffffffffu, rs, off);
            l_run[i] = l_run[i] * alpha[i] + rs;
        }

        // Rescale O (pairs along qi)
        #pragma unroll
        for (int p = 0; p < 4; p++) {
            ull ap = pack2(alpha[2 * p], alpha[2 * p + 1]);
            #pragma unroll
            for (int j = 0; j < 4; j++)
                o[p][j] = fmul2(o[p][j], ap);
        }

        // Store P transposed with qi pairs
        #pragma unroll
        for (int j = 0; j < 4; j++)
            #pragma unroll
            for (int p = 0; p < 4; p++)
                *reinterpret_cast<ull*>(&Pt[(tx * 4 + j) * PPAD + ty * 8 + 2 * p]) =
                    pack2(s[2 * p][j], s[2 * p + 1][j]);
        __syncthreads();

        // O += P @ V  (pairs along qi; V duplicated along d)
        #pragma unroll 8
        for (int kj = 0; kj < 64; kj++) {
            ulonglong2 A0 = *reinterpret_cast<const ulonglong2*>(&Pt[kj * PPAD + ty * 8]);
            ulonglong2 A1 = *reinterpret_cast<const ulonglong2*>(&Pt[kj * PPAD + ty * 8 + 4]);
            ulonglong2 B0 = *reinterpret_cast<const ulonglong2*>(&Vd[kj * 128 + tx * 8]);
            ulonglong2 B1 = *reinterpret_cast<const ulonglong2*>(&Vd[kj * 128 + tx * 8 + 4]);
            ull a[4] = {A0.x, A0.y, A1.x, A1.y};
            ull b[4] = {B0.x, B0.y, B1.x, B1.y};
            #pragma unroll
            for (int p = 0; p < 4; p++)
                #pragma unroll
                for (int j = 0; j < 4; j++)
                    o[p][j] = ffma2(a[p], b[j], o[p][j]);
        }
    }

    // Epilogue: normalize, write [B,S,H*DH]
    const int b = bh >> 3;
    const int h = bh & 7;
    #pragma unroll
    for (int p = 0; p < 4; p++) {
        float2 f0 = unpack2(o[p][0]);
        float2 f1 = unpack2(o[p][1]);
        float2 f2 = unpack2(o[p][2]);
        float2 f3 = unpack2(o[p][3]);
        #pragma unroll
        for (int hh = 0; hh < 2; hh++) {
            int i = 2 * p + hh;
            float inv = 1.0f / l_run[i];
            int sI = q0 + ty * 8 + i;
            float4 o4 = hh == 0
                ? make_float4(f0.x * inv, f1.x * inv, f2.x * inv, f3.x * inv)
                : make_float4(f0.y * inv, f1.y * inv, f2.y * inv, f3.y * inv);
            *reinterpret_cast<float4*>(
                &out[((b * S_ + sI) * H_ + h) * DH_ + tx * 4]) = o4;
        }
    }
}

extern "C" void kernel_launch(void* const* d_in, const int* in_sizes, int n_in,
                              void* d_out, int out_size)
{
    const float* x  = (const float*)d_in[0];
    const float* Wq = (const float*)d_in[1];
    const float* Wk = (const float*)d_in[2];
    const float* Wv = (const float*)d_in[3];
    float* out = (float*)d_out;

    cudaFuncSetAttribute(attn_kernel,
                         cudaFuncAttributeMaxDynamicSharedMemorySize, ATTN_SMEM);

    qkv_kernel<<<dim3((B_ * S_) / 128, 3 * H_), 256>>>(x, Wq, Wk, Wv);
    attn_kernel<<<dim3(S_ / 128, BH_), 256, ATTN_SMEM>>>(out);
}